// round 2
// baseline (speedup 1.0000x reference)
#include <cuda_runtime.h>
#include <cstdint>

#define B_ 16
#define O_ 64
#define I_ 512
#define D_ 256

// ---------------- scratch (no allocation allowed) ----------------
__device__ float g_qp[B_ * O_ * D_];   // qp' = q@W1q^T + b1   (1 MB)
__device__ float g_kp[B_ * I_ * D_];   // kp  = k@W1k^T        (8 MB)

// ---------------- projection GEMM: Y[m][h] = sum_d X[m][d] * W1[h][colOff+d] (+b1[h]) ----
// tile 64x64, K-chunk 32, 256 threads, 4x4 microtile
__global__ __launch_bounds__(256) void proj_kernel(
    const float* __restrict__ X, const float* __restrict__ W1,
    const float* __restrict__ b1, int colOff, int isK)
{
    float* __restrict__ Y = isK ? g_kp : g_qp;
    __shared__ float Xs[32][68];   // [k][m], padded, 16B-aligned rows
    __shared__ float Ws[32][68];   // [k][h]

    const int m0 = blockIdx.x * 64;
    const int h0 = blockIdx.y * 64;
    const int tid = threadIdx.x;
    const int tx = tid & 15, ty = tid >> 4;
    const int tx4 = tx * 4, ty4 = ty * 4;

    float acc[4][4];
#pragma unroll
    for (int r = 0; r < 4; r++)
#pragma unroll
        for (int c = 0; c < 4; c++) acc[r][c] = 0.f;

    for (int k0 = 0; k0 < 256; k0 += 32) {
#pragma unroll
        for (int l = 0; l < 2; l++) {
            int f = tid + l * 256;       // 0..511
            int r = f >> 3;              // row 0..63
            int c = (f & 7) << 2;        // col 0,4,...,28
            float4 xv = *(const float4*)(X + (size_t)(m0 + r) * 256 + k0 + c);
            Xs[c + 0][r] = xv.x; Xs[c + 1][r] = xv.y;
            Xs[c + 2][r] = xv.z; Xs[c + 3][r] = xv.w;
            float4 wv = *(const float4*)(W1 + (size_t)(h0 + r) * 512 + colOff + k0 + c);
            Ws[c + 0][r] = wv.x; Ws[c + 1][r] = wv.y;
            Ws[c + 2][r] = wv.z; Ws[c + 3][r] = wv.w;
        }
        __syncthreads();
#pragma unroll
        for (int k = 0; k < 32; k++) {
            float4 a = *(const float4*)&Xs[k][ty4];
            float4 bb = *(const float4*)&Ws[k][tx4];
            float av[4] = {a.x, a.y, a.z, a.w};
            float bv[4] = {bb.x, bb.y, bb.z, bb.w};
#pragma unroll
            for (int r = 0; r < 4; r++)
#pragma unroll
                for (int c = 0; c < 4; c++)
                    acc[r][c] = fmaf(av[r], bv[c], acc[r][c]);
        }
        __syncthreads();
    }

#pragma unroll
    for (int r = 0; r < 4; r++) {
        float4 ov;
        float bias0 = b1 ? b1[h0 + tx4 + 0] : 0.f;
        float bias1 = b1 ? b1[h0 + tx4 + 1] : 0.f;
        float bias2 = b1 ? b1[h0 + tx4 + 2] : 0.f;
        float bias3 = b1 ? b1[h0 + tx4 + 3] : 0.f;
        ov.x = acc[r][0] + bias0;
        ov.y = acc[r][1] + bias1;
        ov.z = acc[r][2] + bias2;
        ov.w = acc[r][3] + bias3;
        *(float4*)(Y + (size_t)(m0 + ty4 + r) * 256 + h0 + tx4) = ov;
    }
}

// ---------------- fast tanh on the FMA pipe (no MUFU) ----------------
// Eigen/TensorFlow 13/6 rational minimax; reciprocal by bit-hack + 3 Newton (pure FMA).
__device__ __forceinline__ float fast_tanh(float x)
{
    x = fminf(fmaxf(x, -7.90531110763549805f), 7.90531110763549805f);
    const float x2 = x * x;
    float p = fmaf(x2, -2.76076847742355e-16f, 2.00018790482477e-13f);
    p = fmaf(p, x2, -8.60467152213735e-11f);
    p = fmaf(p, x2, 5.12229709037114e-08f);
    p = fmaf(p, x2, 1.48572235717979e-05f);
    p = fmaf(p, x2, 6.37261928875436e-04f);
    p = fmaf(p, x2, 4.89352455891786e-03f);
    p = p * x;
    float q = fmaf(x2, 1.19825839466702e-06f, 1.18534705686654e-04f);
    q = fmaf(q, x2, 2.26843463243900e-03f);
    q = fmaf(q, x2, 4.89352518554385e-03f);
    // 1/q, q in (0.004, 1): bit-hack seed + 3 Newton steps (FMA pipe only)
    float r = __int_as_float(0x7EF311C3u - __float_as_int(q));
    r = r * fmaf(-q, r, 2.0f);
    r = r * fmaf(-q, r, 2.0f);
    r = r * fmaf(-q, r, 2.0f);
    return p * r;
}

// ---------------- main kernel: one block per (b,o) ----------------
__global__ __launch_bounds__(256) void attn_kernel(
    const float* __restrict__ v, const int* __restrict__ mask,
    const float* __restrict__ W2, const float* __restrict__ Wf,
    const float* __restrict__ bf,
    float* __restrict__ out, float* __restrict__ attn_out)
{
    __shared__ float s_scores[I_];
    __shared__ float s_redA[8];
    __shared__ float s_redB[8];
    __shared__ float s_pre[D_];

    const int b = blockIdx.x >> 6;
    const int o = blockIdx.x & 63;
    const int tid = threadIdx.x;
    const int lane = tid & 31;
    const int warp = tid >> 5;
    const int hb = lane * 8;        // this lane covers h = hb .. hb+7

    // per-lane invariants: qp'[b,o,hb..hb+7], W2[hb..hb+7]
    const float4* qp4 = (const float4*)(g_qp + ((size_t)(b * O_ + o)) * 256 + hb);
    float4 qa = qp4[0], qb = qp4[1];
    const float4* w24 = (const float4*)(W2 + hb);
    float4 wa = w24[0], wb = w24[1];
    float qph[8] = {qa.x, qa.y, qa.z, qa.w, qb.x, qb.y, qb.z, qb.w};
    float w2h[8] = {wa.x, wa.y, wa.z, wa.w, wb.x, wb.y, wb.z, wb.w};

    // ---- phase 1: scores ----
    for (int i = warp; i < I_; i += 8) {
        const float4* kr = (const float4*)(g_kp + ((size_t)(b * I_ + i)) * 256 + hb);
        float4 k0 = kr[0], k1 = kr[1];
        float kv[8] = {k0.x, k0.y, k0.z, k0.w, k1.x, k1.y, k1.z, k1.w};
        float s = 0.f;
#pragma unroll
        for (int j = 0; j < 8; j++)
            s = fmaf(fast_tanh(qph[j] + kv[j]), w2h[j], s);
#pragma unroll
        for (int off = 16; off > 0; off >>= 1)
            s += __shfl_xor_sync(0xffffffffu, s, off);
        if (lane == 0) s_scores[i] = s;
    }
    __syncthreads();

    // ---- phase 2: masked softmax (mask is int32: nonzero -> -inf) ----
    const int* mrow = mask + b * I_;
    float sc0 = s_scores[tid];
    float sc1 = s_scores[tid + 256];
    if (mrow[tid])       sc0 = -1e30f;
    if (mrow[tid + 256]) sc1 = -1e30f;
    float m = fmaxf(sc0, sc1);
#pragma unroll
    for (int off = 16; off > 0; off >>= 1)
        m = fmaxf(m, __shfl_xor_sync(0xffffffffu, m, off));
    if (lane == 0) s_redA[warp] = m;
    __syncthreads();
    float mx = s_redA[0];
#pragma unroll
    for (int j = 1; j < 8; j++) mx = fmaxf(mx, s_redA[j]);

    float e0 = __expf(sc0 - mx);
    float e1 = __expf(sc1 - mx);
    float ssum = e0 + e1;
#pragma unroll
    for (int off = 16; off > 0; off >>= 1)
        ssum += __shfl_xor_sync(0xffffffffu, ssum, off);
    if (lane == 0) s_redB[warp] = ssum;
    __syncthreads();
    float tot = 0.f;
#pragma unroll
    for (int j = 0; j < 8; j++) tot += s_redB[j];
    float inv = __fdividef(1.0f, tot);
    float p0 = e0 * inv, p1 = e1 * inv;
    __syncthreads();               // everyone done reading s_scores as scores
    s_scores[tid] = p0;
    s_scores[tid + 256] = p1;
    float* arow = attn_out + ((size_t)(b * O_ + o)) * I_;
    arow[tid] = p0;
    arow[tid + 256] = p1;
    __syncthreads();

    // ---- phase 3: pre = attn @ v ----
    {
        float acc = 0.f;
        const float* vb = v + (size_t)b * I_ * D_ + tid;
#pragma unroll 4
        for (int i = 0; i < I_; i++)
            acc = fmaf(s_scores[i], vb[(size_t)i * D_], acc);
        s_pre[tid] = acc;
    }
    __syncthreads();

    // ---- phase 4: out = leaky(pre @ Wf^T + bf) ----
    float pr[8];
#pragma unroll
    for (int j = 0; j < 8; j++) pr[j] = s_pre[hb + j];

    float outv = 0.f;
    for (int c = 0; c < 32; c++) {
        int d = (warp << 5) + c;
        const float4* wf = (const float4*)(Wf + (size_t)d * 256 + hb);
        float4 f0 = wf[0], f1 = wf[1];
        float s = pr[0] * f0.x;
        s = fmaf(pr[1], f0.y, s);
        s = fmaf(pr[2], f0.z, s);
        s = fmaf(pr[3], f0.w, s);
        s = fmaf(pr[4], f1.x, s);
        s = fmaf(pr[5], f1.y, s);
        s = fmaf(pr[6], f1.z, s);
        s = fmaf(pr[7], f1.w, s);
#pragma unroll
        for (int off = 16; off > 0; off >>= 1)
            s += __shfl_xor_sync(0xffffffffu, s, off);
        if (lane == c) outv = s;
    }
    int d = (warp << 5) + lane;
    float f = outv + bf[d];
    f = (f >= 0.f) ? f : 0.01f * f;
    out[((size_t)(b * O_ + o)) * D_ + d] = f;
}

// ---------------- launch ----------------
extern "C" void kernel_launch(void* const* d_in, const int* in_sizes, int n_in,
                              void* d_out, int out_size)
{
    const float* q  = (const float*)d_in[0];
    const float* k  = (const float*)d_in[1];
    const float* v  = (const float*)d_in[2];
    const int* mask = (const int*)d_in[3];
    const float* W1 = (const float*)d_in[4];
    const float* b1 = (const float*)d_in[5];
    const float* W2 = (const float*)d_in[6];
    // b2 = d_in[7]: additive constant on scores -> cancels in softmax, score not returned
    const float* Wf = (const float*)d_in[8];
    const float* bf = (const float*)d_in[9];

    float* out  = (float*)d_out;                    // (16,64,256)
    float* attn = out + (size_t)B_ * O_ * D_;       // (16,64,512)

    // qp' = q @ W1[:, :D]^T + b1   (M = 1024)
    {
        dim3 g(B_ * O_ / 64, D_ / 64);
        proj_kernel<<<g, 256>>>(q, W1, b1, 0, 0);
    }
    // kp = k @ W1[:, D:]^T         (M = 8192)
    {
        dim3 g(B_ * I_ / 64, D_ / 64);
        proj_kernel<<<g, 256>>>(k, W1, nullptr, D_, 1);
    }
    attn_kernel<<<B_ * O_, 256>>>(v, mask, W2, Wf, bf, out, attn);
}

// round 3
// speedup vs baseline: 1.2095x; 1.2095x over previous
#include <cuda_runtime.h>
#include <cstdint>

#define B_ 16
#define O_ 64
#define I_ 512
#define D_ 256
#define OPB 4    // o-values per attn block

// ---------------- scratch (no allocation allowed) ----------------
__device__ float g_qp[B_ * O_ * D_];    // [b][o][h]  qp' = q@W1q^T + b1
__device__ float g_kpt[B_ * D_ * I_];   // [b][h][i]  kp^T (transposed!)

// ---------------- merged projection GEMM ----------------
// blocks 0..63   : qp  (16 m-tiles x 4 h-tiles), row-major out + b1
// blocks 64..575 : kp  (128 m-tiles x 4 h-tiles), transposed out
__global__ __launch_bounds__(256) void proj_kernel(
    const float* __restrict__ q, const float* __restrict__ k,
    const float* __restrict__ W1, const float* __restrict__ b1)
{
    __shared__ float Xs[32][68];
    __shared__ float Ws[32][68];

    const int bid = blockIdx.x;
    const bool isK = (bid >= 64);
    const int rb = isK ? bid - 64 : bid;
    const int m0 = (rb >> 2) * 64;
    const int h0 = (rb & 3) * 64;
    const float* __restrict__ X = isK ? k : q;
    const int colOff = isK ? 256 : 0;

    const int tid = threadIdx.x;
    const int tx = tid & 15, ty = tid >> 4;
    const int tx4 = tx * 4, ty4 = ty * 4;

    float acc[4][4];
#pragma unroll
    for (int r = 0; r < 4; r++)
#pragma unroll
        for (int c = 0; c < 4; c++) acc[r][c] = 0.f;

    for (int k0 = 0; k0 < 256; k0 += 32) {
#pragma unroll
        for (int l = 0; l < 2; l++) {
            int f = tid + l * 256;
            int r = f >> 3;
            int c = (f & 7) << 2;
            float4 xv = *(const float4*)(X + (size_t)(m0 + r) * 256 + k0 + c);
            Xs[c + 0][r] = xv.x; Xs[c + 1][r] = xv.y;
            Xs[c + 2][r] = xv.z; Xs[c + 3][r] = xv.w;
            float4 wv = *(const float4*)(W1 + (size_t)(h0 + r) * 512 + colOff + k0 + c);
            Ws[c + 0][r] = wv.x; Ws[c + 1][r] = wv.y;
            Ws[c + 2][r] = wv.z; Ws[c + 3][r] = wv.w;
        }
        __syncthreads();
#pragma unroll
        for (int kk = 0; kk < 32; kk++) {
            float4 a = *(const float4*)&Xs[kk][ty4];
            float4 bb = *(const float4*)&Ws[kk][tx4];
            float av[4] = {a.x, a.y, a.z, a.w};
            float bv[4] = {bb.x, bb.y, bb.z, bb.w};
#pragma unroll
            for (int r = 0; r < 4; r++)
#pragma unroll
                for (int c = 0; c < 4; c++)
                    acc[r][c] = fmaf(av[r], bv[c], acc[r][c]);
        }
        __syncthreads();
    }

    if (!isK) {
        // qp: row-major + b1
#pragma unroll
        for (int r = 0; r < 4; r++) {
            float4 ov;
            ov.x = acc[r][0] + b1[h0 + tx4 + 0];
            ov.y = acc[r][1] + b1[h0 + tx4 + 1];
            ov.z = acc[r][2] + b1[h0 + tx4 + 2];
            ov.w = acc[r][3] + b1[h0 + tx4 + 3];
            *(float4*)(g_qp + (size_t)(m0 + ty4 + r) * 256 + h0 + tx4) = ov;
        }
    } else {
        // kp: transposed store [b][h][i]
        const int b = m0 >> 9;
        const int i0 = (m0 & 511) + ty4;
#pragma unroll
        for (int c = 0; c < 4; c++) {
            int h = h0 + tx4 + c;
            float4 ov = make_float4(acc[0][c], acc[1][c], acc[2][c], acc[3][c]);
            *(float4*)(g_kpt + ((size_t)(b * 256 + h) << 9) + i0) = ov;
        }
    }
}

// ---------------- hardware tanh (MUFU.TANH) ----------------
__device__ __forceinline__ float tanh_fast(float x)
{
    float y;
    asm("tanh.approx.f32 %0, %1;" : "=f"(y) : "f"(x));
    return y;
}

// ---------------- main kernel: one block per (b, 4 o's) ----------------
__global__ __launch_bounds__(256) void attn_kernel(
    const float* __restrict__ v, const int* __restrict__ mask,
    const float* __restrict__ W2, const float* __restrict__ Wf,
    const float* __restrict__ bf,
    float* __restrict__ out, float* __restrict__ attn_out)
{
    __shared__ float s_sc[OPB][I_];     // scores -> probs
    __shared__ float s_qp[OPB][D_];
    __shared__ float s_w2[D_];
    __shared__ float s_pre[OPB][D_];
    __shared__ float s_redA[OPB][8];
    __shared__ float s_redB[OPB][8];

    const int b = blockIdx.x >> 4;
    const int o0 = (blockIdx.x & 15) << 2;
    const int tid = threadIdx.x;
    const int lane = tid & 31;
    const int warp = tid >> 5;

    // stage qp rows (contiguous 4*256 floats) and W2
    {
        const float* src = g_qp + ((size_t)(b * O_ + o0) << 8);
        float4 t0 = ((const float4*)src)[tid];           // 256 thr * 4 = 1024 floats
        ((float4*)&s_qp[0][0])[tid] = t0;
        if (tid < 64) ((float4*)s_w2)[tid] = ((const float4*)W2)[tid];
    }
    __syncthreads();

    // ---- phase 1: scores, lane = i (coalesced, no shuffles) ----
    const float* kpt = g_kpt + ((size_t)b << 17);   // b * 256*512
#pragma unroll
    for (int half = 0; half < 2; half++) {
        const int i = (warp << 6) + (half << 5) + lane;
        float a0 = 0.f, a1 = 0.f, a2 = 0.f, a3 = 0.f;
#pragma unroll 2
        for (int h = 0; h < D_; h += 4) {
            float4 w2 = *(const float4*)&s_w2[h];
            float4 q0 = *(const float4*)&s_qp[0][h];
            float4 q1 = *(const float4*)&s_qp[1][h];
            float4 q2 = *(const float4*)&s_qp[2][h];
            float4 q3 = *(const float4*)&s_qp[3][h];
            float kv0 = kpt[((h + 0) << 9) + i];
            float kv1 = kpt[((h + 1) << 9) + i];
            float kv2 = kpt[((h + 2) << 9) + i];
            float kv3 = kpt[((h + 3) << 9) + i];
            a0 = fmaf(tanh_fast(q0.x + kv0), w2.x, a0);
            a1 = fmaf(tanh_fast(q1.x + kv0), w2.x, a1);
            a2 = fmaf(tanh_fast(q2.x + kv0), w2.x, a2);
            a3 = fmaf(tanh_fast(q3.x + kv0), w2.x, a3);
            a0 = fmaf(tanh_fast(q0.y + kv1), w2.y, a0);
            a1 = fmaf(tanh_fast(q1.y + kv1), w2.y, a1);
            a2 = fmaf(tanh_fast(q2.y + kv1), w2.y, a2);
            a3 = fmaf(tanh_fast(q3.y + kv1), w2.y, a3);
            a0 = fmaf(tanh_fast(q0.z + kv2), w2.z, a0);
            a1 = fmaf(tanh_fast(q1.z + kv2), w2.z, a1);
            a2 = fmaf(tanh_fast(q2.z + kv2), w2.z, a2);
            a3 = fmaf(tanh_fast(q3.z + kv2), w2.z, a3);
            a0 = fmaf(tanh_fast(q0.w + kv3), w2.w, a0);
            a1 = fmaf(tanh_fast(q1.w + kv3), w2.w, a1);
            a2 = fmaf(tanh_fast(q2.w + kv3), w2.w, a2);
            a3 = fmaf(tanh_fast(q3.w + kv3), w2.w, a3);
        }
        s_sc[0][i] = a0;
        s_sc[1][i] = a1;
        s_sc[2][i] = a2;
        s_sc[3][i] = a3;
    }
    __syncthreads();

    // ---- phase 2: masked softmax for 4 o's ----
    const int* mrow = mask + b * I_;
    const int msk0 = mrow[tid];
    const int msk1 = mrow[tid + 256];
    float sc0[OPB], sc1[OPB], e0[OPB], e1[OPB];
#pragma unroll
    for (int oo = 0; oo < OPB; oo++) {
        sc0[oo] = msk0 ? -1e30f : s_sc[oo][tid];
        sc1[oo] = msk1 ? -1e30f : s_sc[oo][tid + 256];
        float m = fmaxf(sc0[oo], sc1[oo]);
#pragma unroll
        for (int off = 16; off > 0; off >>= 1)
            m = fmaxf(m, __shfl_xor_sync(0xffffffffu, m, off));
        if (lane == 0) s_redA[oo][warp] = m;
    }
    __syncthreads();
#pragma unroll
    for (int oo = 0; oo < OPB; oo++) {
        float mx = s_redA[oo][0];
#pragma unroll
        for (int j = 1; j < 8; j++) mx = fmaxf(mx, s_redA[oo][j]);
        e0[oo] = __expf(sc0[oo] - mx);
        e1[oo] = __expf(sc1[oo] - mx);
        float ssum = e0[oo] + e1[oo];
#pragma unroll
        for (int off = 16; off > 0; off >>= 1)
            ssum += __shfl_xor_sync(0xffffffffu, ssum, off);
        if (lane == 0) s_redB[oo][warp] = ssum;
    }
    __syncthreads();
#pragma unroll
    for (int oo = 0; oo < OPB; oo++) {
        float tot = 0.f;
#pragma unroll
        for (int j = 0; j < 8; j++) tot += s_redB[oo][j];
        float inv = __fdividef(1.0f, tot);
        float p0 = e0[oo] * inv, p1 = e1[oo] * inv;
        s_sc[oo][tid] = p0;
        s_sc[oo][tid + 256] = p1;
        float* arow = attn_out + ((size_t)(b * O_ + o0 + oo) << 9);
        arow[tid] = p0;
        arow[tid + 256] = p1;
    }
    __syncthreads();

    // ---- phase 3: pre = attn @ v (v loaded once per 4 o's) ----
    {
        float ac0 = 0.f, ac1 = 0.f, ac2 = 0.f, ac3 = 0.f;
        const float* vb = v + ((size_t)b << 17) + tid;   // b * 512*256
#pragma unroll 2
        for (int i = 0; i < I_; i += 4) {
            float4 p0 = *(const float4*)&s_sc[0][i];
            float4 p1 = *(const float4*)&s_sc[1][i];
            float4 p2 = *(const float4*)&s_sc[2][i];
            float4 p3 = *(const float4*)&s_sc[3][i];
            float v0 = vb[(i + 0) << 8];
            float v1 = vb[(i + 1) << 8];
            float v2 = vb[(i + 2) << 8];
            float v3 = vb[(i + 3) << 8];
            ac0 = fmaf(p0.x, v0, ac0); ac1 = fmaf(p1.x, v0, ac1);
            ac2 = fmaf(p2.x, v0, ac2); ac3 = fmaf(p3.x, v0, ac3);
            ac0 = fmaf(p0.y, v1, ac0); ac1 = fmaf(p1.y, v1, ac1);
            ac2 = fmaf(p2.y, v1, ac2); ac3 = fmaf(p3.y, v1, ac3);
            ac0 = fmaf(p0.z, v2, ac0); ac1 = fmaf(p1.z, v2, ac1);
            ac2 = fmaf(p2.z, v2, ac2); ac3 = fmaf(p3.z, v2, ac3);
            ac0 = fmaf(p0.w, v3, ac0); ac1 = fmaf(p1.w, v3, ac1);
            ac2 = fmaf(p2.w, v3, ac2); ac3 = fmaf(p3.w, v3, ac3);
        }
        s_pre[0][tid] = ac0;
        s_pre[1][tid] = ac1;
        s_pre[2][tid] = ac2;
        s_pre[3][tid] = ac3;
    }
    __syncthreads();

    // ---- phase 4: out = leaky(pre @ Wf^T + bf), Wf loads shared by 4 o's ----
    const int hb = lane * 8;
    float pr0[8], pr1[8], pr2[8], pr3[8];
#pragma unroll
    for (int j = 0; j < 8; j++) {
        pr0[j] = s_pre[0][hb + j];
        pr1[j] = s_pre[1][hb + j];
        pr2[j] = s_pre[2][hb + j];
        pr3[j] = s_pre[3][hb + j];
    }

    float ov0 = 0.f, ov1 = 0.f, ov2 = 0.f, ov3 = 0.f;
    for (int c = 0; c < 32; c++) {
        const int d = (warp << 5) + c;
        const float4* wf = (const float4*)(Wf + ((size_t)d << 8) + hb);
        float4 f0 = wf[0], f1 = wf[1];
        float fr[8] = {f0.x, f0.y, f0.z, f0.w, f1.x, f1.y, f1.z, f1.w};
        float s0 = 0.f, s1 = 0.f, s2 = 0.f, s3 = 0.f;
#pragma unroll
        for (int j = 0; j < 8; j++) {
            s0 = fmaf(pr0[j], fr[j], s0);
            s1 = fmaf(pr1[j], fr[j], s1);
            s2 = fmaf(pr2[j], fr[j], s2);
            s3 = fmaf(pr3[j], fr[j], s3);
        }
#pragma unroll
        for (int off = 16; off > 0; off >>= 1) {
            s0 += __shfl_xor_sync(0xffffffffu, s0, off);
            s1 += __shfl_xor_sync(0xffffffffu, s1, off);
            s2 += __shfl_xor_sync(0xffffffffu, s2, off);
            s3 += __shfl_xor_sync(0xffffffffu, s3, off);
        }
        if (lane == c) { ov0 = s0; ov1 = s1; ov2 = s2; ov3 = s3; }
    }
    const int d = (warp << 5) + lane;
    const float bfd = bf[d];
    float f0v = ov0 + bfd; f0v = (f0v >= 0.f) ? f0v : 0.01f * f0v;
    float f1v = ov1 + bfd; f1v = (f1v >= 0.f) ? f1v : 0.01f * f1v;
    float f2v = ov2 + bfd; f2v = (f2v >= 0.f) ? f2v : 0.01f * f2v;
    float f3v = ov3 + bfd; f3v = (f3v >= 0.f) ? f3v : 0.01f * f3v;
    out[((size_t)(b * O_ + o0 + 0) << 8) + d] = f0v;
    out[((size_t)(b * O_ + o0 + 1) << 8) + d] = f1v;
    out[((size_t)(b * O_ + o0 + 2) << 8) + d] = f2v;
    out[((size_t)(b * O_ + o0 + 3) << 8) + d] = f3v;
}

// ---------------- launch ----------------
extern "C" void kernel_launch(void* const* d_in, const int* in_sizes, int n_in,
                              void* d_out, int out_size)
{
    const float* q  = (const float*)d_in[0];
    const float* k  = (const float*)d_in[1];
    const float* v  = (const float*)d_in[2];
    const int* mask = (const int*)d_in[3];
    const float* W1 = (const float*)d_in[4];
    const float* b1 = (const float*)d_in[5];
    const float* W2 = (const float*)d_in[6];
    // b2 (d_in[7]) cancels in softmax
    const float* Wf = (const float*)d_in[8];
    const float* bf = (const float*)d_in[9];

    float* out  = (float*)d_out;                  // (16,64,256)
    float* attn = out + (size_t)B_ * O_ * D_;     // (16,64,512)

    proj_kernel<<<576, 256>>>(q, k, W1, b1);
    attn_kernel<<<B_ * (O_ / OPB), 256>>>(v, mask, W2, Wf, bf, out, attn);
}

// round 4
// speedup vs baseline: 1.8959x; 1.5676x over previous
#include <cuda_runtime.h>
#include <cstdint>

#define B_ 16
#define O_ 64
#define I_ 512
#define D_ 256
#define OPB 4    // o-values per score/finish block group

// ---------------- scratch (no allocation allowed) ----------------
__device__ float g_qp[B_ * O_ * D_];    // [b][o][h]  qp' = q@W1q^T + b1
__device__ float g_kpt[B_ * D_ * I_];   // [b][h][i]  kp^T
__device__ float g_sc[B_ * O_ * I_];    // [b][o][i]  raw scores

// ---------------- merged projection GEMM ----------------
// blocks 0..63   : qp  (16 m-tiles x 4 h-tiles), row-major out + b1
// blocks 64..575 : kp  (128 m-tiles x 4 h-tiles), transposed out
__global__ __launch_bounds__(256) void proj_kernel(
    const float* __restrict__ q, const float* __restrict__ k,
    const float* __restrict__ W1, const float* __restrict__ b1)
{
    __shared__ __align__(16) float Xs[32][68];
    __shared__ __align__(16) float Ws[32][68];

    const int bid = blockIdx.x;
    const bool isK = (bid >= 64);
    const int rb = isK ? bid - 64 : bid;
    const int m0 = (rb >> 2) * 64;
    const int h0 = (rb & 3) * 64;
    const float* __restrict__ X = isK ? k : q;
    const int colOff = isK ? 256 : 0;

    const int tid = threadIdx.x;
    const int tx = tid & 15, ty = tid >> 4;
    const int tx4 = tx * 4, ty4 = ty * 4;

    float acc[4][4];
#pragma unroll
    for (int r = 0; r < 4; r++)
#pragma unroll
        for (int c = 0; c < 4; c++) acc[r][c] = 0.f;

    for (int k0 = 0; k0 < 256; k0 += 32) {
#pragma unroll
        for (int l = 0; l < 2; l++) {
            int f = tid + l * 256;
            int r = f >> 3;
            int c = (f & 7) << 2;
            float4 xv = *(const float4*)(X + (size_t)(m0 + r) * 256 + k0 + c);
            Xs[c + 0][r] = xv.x; Xs[c + 1][r] = xv.y;
            Xs[c + 2][r] = xv.z; Xs[c + 3][r] = xv.w;
            float4 wv = *(const float4*)(W1 + (size_t)(h0 + r) * 512 + colOff + k0 + c);
            Ws[c + 0][r] = wv.x; Ws[c + 1][r] = wv.y;
            Ws[c + 2][r] = wv.z; Ws[c + 3][r] = wv.w;
        }
        __syncthreads();
#pragma unroll
        for (int kk = 0; kk < 32; kk++) {
            float4 a = *(const float4*)&Xs[kk][ty4];
            float4 bb = *(const float4*)&Ws[kk][tx4];
            float av[4] = {a.x, a.y, a.z, a.w};
            float bv[4] = {bb.x, bb.y, bb.z, bb.w};
#pragma unroll
            for (int r = 0; r < 4; r++)
#pragma unroll
                for (int c = 0; c < 4; c++)
                    acc[r][c] = fmaf(av[r], bv[c], acc[r][c]);
        }
        __syncthreads();
    }

    if (!isK) {
#pragma unroll
        for (int r = 0; r < 4; r++) {
            float4 ov;
            ov.x = acc[r][0] + b1[h0 + tx4 + 0];
            ov.y = acc[r][1] + b1[h0 + tx4 + 1];
            ov.z = acc[r][2] + b1[h0 + tx4 + 2];
            ov.w = acc[r][3] + b1[h0 + tx4 + 3];
            *(float4*)(g_qp + (size_t)(m0 + ty4 + r) * 256 + h0 + tx4) = ov;
        }
    } else {
        const int b = m0 >> 9;
        const int i0 = (m0 & 511) + ty4;
#pragma unroll
        for (int c = 0; c < 4; c++) {
            int h = h0 + tx4 + c;
            float4 ov = make_float4(acc[0][c], acc[1][c], acc[2][c], acc[3][c]);
            *(float4*)(g_kpt + ((size_t)(b * 256 + h) << 9) + i0) = ov;
        }
    }
}

// ---------------- hardware tanh (MUFU.TANH) ----------------
__device__ __forceinline__ float tanh_fast(float x)
{
    float y;
    asm("tanh.approx.f32 %0, %1;" : "=f"(y) : "f"(x));
    return y;
}

// ---------------- score kernel: grid 1024 = b(16) x o-group(16) x i-chunk(4) ----
// 128 threads; thread = one i; 4 o accumulators; h-loop over 256 with unroll 8.
__global__ __launch_bounds__(128) void score_kernel(const float* __restrict__ W2)
{
    __shared__ __align__(16) float s_qp[OPB][D_];
    __shared__ __align__(16) float s_w2[D_];

    const int bx = blockIdx.x;
    const int b  = bx >> 6;
    const int og = (bx >> 2) & 15;
    const int ic = bx & 3;
    const int o0 = og << 2;
    const int tid = threadIdx.x;

    // stage qp (4x256) and W2
    {
        const float4* src = (const float4*)(g_qp + ((size_t)(b * O_ + o0) << 8));
        ((float4*)s_qp)[tid]       = src[tid];
        ((float4*)s_qp)[tid + 128] = src[tid + 128];
        if (tid < 64) ((float4*)s_w2)[tid] = ((const float4*)W2)[tid];
    }
    __syncthreads();

    const int i = (ic << 7) + tid;
    const float* kpt = g_kpt + ((size_t)b << 17) + i;

    float a0 = 0.f, a1 = 0.f, a2 = 0.f, a3 = 0.f;
    for (int h = 0; h < D_; h += 8) {
        float kv[8];
#pragma unroll
        for (int j = 0; j < 8; j++)
            kv[j] = kpt[(size_t)(h + j) << 9];
#pragma unroll
        for (int j = 0; j < 8; j++) {
            const float w = s_w2[h + j];
            a0 = fmaf(tanh_fast(s_qp[0][h + j] + kv[j]), w, a0);
            a1 = fmaf(tanh_fast(s_qp[1][h + j] + kv[j]), w, a1);
            a2 = fmaf(tanh_fast(s_qp[2][h + j] + kv[j]), w, a2);
            a3 = fmaf(tanh_fast(s_qp[3][h + j] + kv[j]), w, a3);
        }
    }
    float* dst = g_sc + ((size_t)(b * O_ + o0) << 9) + i;
    dst[0 << 9] = a0;
    dst[1 << 9] = a1;
    dst[2 << 9] = a2;
    dst[3 << 9] = a3;
}

// ---------------- finish kernel: softmax + attn@v + Wf. grid 256, 512 threads ----
__global__ __launch_bounds__(512) void finish_kernel(
    const float* __restrict__ v, const int* __restrict__ mask,
    const float* __restrict__ Wf, const float* __restrict__ bf,
    float* __restrict__ out, float* __restrict__ attn_out)
{
    __shared__ __align__(16) float s_p[OPB][I_];        // probs (8KB)
    __shared__ __align__(16) float s_part[2][OPB][D_];  // 8KB
    __shared__ __align__(16) float s_pre[OPB][D_];      // 4KB
    __shared__ float s_redA[OPB][16];
    __shared__ float s_redB[OPB][16];

    const int b  = blockIdx.x >> 4;
    const int o0 = (blockIdx.x & 15) << 2;
    const int tid = threadIdx.x;
    const int lane = tid & 31;
    const int warp = tid >> 5;      // 0..15

    // ---- softmax over i (tid = i) ----
    const int msk = mask[b * I_ + tid];
    const float* scp = g_sc + ((size_t)(b * O_ + o0) << 9) + tid;
    float sc[OPB], e[OPB];
#pragma unroll
    for (int oo = 0; oo < OPB; oo++) {
        sc[oo] = msk ? -1e30f : scp[(size_t)oo << 9];
        float m = sc[oo];
#pragma unroll
        for (int off = 16; off > 0; off >>= 1)
            m = fmaxf(m, __shfl_xor_sync(0xffffffffu, m, off));
        if (lane == 0) s_redA[oo][warp] = m;
    }
    __syncthreads();
#pragma unroll
    for (int oo = 0; oo < OPB; oo++) {
        float mx = s_redA[oo][0];
#pragma unroll
        for (int j = 1; j < 16; j++) mx = fmaxf(mx, s_redA[oo][j]);
        e[oo] = __expf(sc[oo] - mx);
        float ssum = e[oo];
#pragma unroll
        for (int off = 16; off > 0; off >>= 1)
            ssum += __shfl_xor_sync(0xffffffffu, ssum, off);
        if (lane == 0) s_redB[oo][warp] = ssum;
    }
    __syncthreads();
#pragma unroll
    for (int oo = 0; oo < OPB; oo++) {
        float tot = 0.f;
#pragma unroll
        for (int j = 0; j < 16; j++) tot += s_redB[oo][j];
        const float p = e[oo] * __fdividef(1.0f, tot);
        s_p[oo][tid] = p;
        attn_out[((size_t)(b * O_ + o0 + oo) << 9) + tid] = p;
    }
    __syncthreads();

    // ---- pre = attn @ v, i-range split across thread halves ----
    {
        const int half = tid >> 8;      // 0/1
        const int d = tid & 255;
        const float* vb = v + ((size_t)b << 17) + ((size_t)half << 16) + d;
        float ac0 = 0.f, ac1 = 0.f, ac2 = 0.f, ac3 = 0.f;
#pragma unroll 2
        for (int ii = 0; ii < 256; ii += 4) {
            const int i = (half << 8) + ii;
            float4 p0 = *(const float4*)&s_p[0][i];
            float4 p1 = *(const float4*)&s_p[1][i];
            float4 p2 = *(const float4*)&s_p[2][i];
            float4 p3 = *(const float4*)&s_p[3][i];
            float v0 = vb[(ii + 0) << 8];
            float v1 = vb[(ii + 1) << 8];
            float v2 = vb[(ii + 2) << 8];
            float v3 = vb[(ii + 3) << 8];
            ac0 = fmaf(p0.x, v0, ac0); ac1 = fmaf(p1.x, v0, ac1);
            ac2 = fmaf(p2.x, v0, ac2); ac3 = fmaf(p3.x, v0, ac3);
            ac0 = fmaf(p0.y, v1, ac0); ac1 = fmaf(p1.y, v1, ac1);
            ac2 = fmaf(p2.y, v1, ac2); ac3 = fmaf(p3.y, v1, ac3);
            ac0 = fmaf(p0.z, v2, ac0); ac1 = fmaf(p1.z, v2, ac1);
            ac2 = fmaf(p2.z, v2, ac2); ac3 = fmaf(p3.z, v2, ac3);
            ac0 = fmaf(p0.w, v3, ac0); ac1 = fmaf(p1.w, v3, ac1);
            ac2 = fmaf(p2.w, v3, ac2); ac3 = fmaf(p3.w, v3, ac3);
        }
        s_part[half][0][d] = ac0;
        s_part[half][1][d] = ac1;
        s_part[half][2][d] = ac2;
        s_part[half][3][d] = ac3;
    }
    __syncthreads();
    if (tid < 256) {
#pragma unroll
        for (int oo = 0; oo < OPB; oo++)
            s_pre[oo][tid] = s_part[0][oo][tid] + s_part[1][oo][tid];
    }
    __syncthreads();

    // ---- out = leaky(pre @ Wf^T + bf), 16 warps x 16 d-columns each ----
    const int hb = lane * 8;
    float pr0[8], pr1[8], pr2[8], pr3[8];
#pragma unroll
    for (int j = 0; j < 8; j++) {
        pr0[j] = s_pre[0][hb + j];
        pr1[j] = s_pre[1][hb + j];
        pr2[j] = s_pre[2][hb + j];
        pr3[j] = s_pre[3][hb + j];
    }

    float ov0 = 0.f, ov1 = 0.f, ov2 = 0.f, ov3 = 0.f;
    for (int c = 0; c < 16; c++) {
        const int d = (warp << 4) + c;
        const float4* wf = (const float4*)(Wf + ((size_t)d << 8) + hb);
        float4 f0 = wf[0], f1 = wf[1];
        float fr[8] = {f0.x, f0.y, f0.z, f0.w, f1.x, f1.y, f1.z, f1.w};
        float s0 = 0.f, s1 = 0.f, s2 = 0.f, s3 = 0.f;
#pragma unroll
        for (int j = 0; j < 8; j++) {
            s0 = fmaf(pr0[j], fr[j], s0);
            s1 = fmaf(pr1[j], fr[j], s1);
            s2 = fmaf(pr2[j], fr[j], s2);
            s3 = fmaf(pr3[j], fr[j], s3);
        }
#pragma unroll
        for (int off = 16; off > 0; off >>= 1) {
            s0 += __shfl_xor_sync(0xffffffffu, s0, off);
            s1 += __shfl_xor_sync(0xffffffffu, s1, off);
            s2 += __shfl_xor_sync(0xffffffffu, s2, off);
            s3 += __shfl_xor_sync(0xffffffffu, s3, off);
        }
        if (lane == c) { ov0 = s0; ov1 = s1; ov2 = s2; ov3 = s3; }
    }
    if (lane < 16) {
        const int d = (warp << 4) + lane;
        const float bfd = bf[d];
        float f0v = ov0 + bfd; f0v = (f0v >= 0.f) ? f0v : 0.01f * f0v;
        float f1v = ov1 + bfd; f1v = (f1v >= 0.f) ? f1v : 0.01f * f1v;
        float f2v = ov2 + bfd; f2v = (f2v >= 0.f) ? f2v : 0.01f * f2v;
        float f3v = ov3 + bfd; f3v = (f3v >= 0.f) ? f3v : 0.01f * f3v;
        out[((size_t)(b * O_ + o0 + 0) << 8) + d] = f0v;
        out[((size_t)(b * O_ + o0 + 1) << 8) + d] = f1v;
        out[((size_t)(b * O_ + o0 + 2) << 8) + d] = f2v;
        out[((size_t)(b * O_ + o0 + 3) << 8) + d] = f3v;
    }
}

// ---------------- launch ----------------
extern "C" void kernel_launch(void* const* d_in, const int* in_sizes, int n_in,
                              void* d_out, int out_size)
{
    const float* q  = (const float*)d_in[0];
    const float* k  = (const float*)d_in[1];
    const float* v  = (const float*)d_in[2];
    const int* mask = (const int*)d_in[3];
    const float* W1 = (const float*)d_in[4];
    const float* b1 = (const float*)d_in[5];
    const float* W2 = (const float*)d_in[6];
    // b2 (d_in[7]) cancels in softmax
    const float* Wf = (const float*)d_in[8];
    const float* bf = (const float*)d_in[9];

    float* out  = (float*)d_out;                  // (16,64,256)
    float* attn = out + (size_t)B_ * O_ * D_;     // (16,64,512)

    proj_kernel<<<576, 256>>>(q, k, W1, b1);
    score_kernel<<<1024, 128>>>(W2);
    finish_kernel<<<256, 512>>>(v, mask, Wf, bf, out, attn);
}